// round 2
// baseline (speedup 1.0000x reference)
#include <cuda_runtime.h>

// Problem constants (from reference): N=1048576 rows, H=128, B=1024 segments.
#define H_DIM 128
#define EPS 1e-12f

// One warp per row. Lane l holds emb[row, 4l..4l+3] as float4.
// seg(row) = searchsorted(ptr[1:], row, side="right")
//          = first s in [0,B) with ptr[s+1] > row.
// NOTE: JAX default config disables x64, so the "int64" ptr array is
// actually int32 on device.
__global__ void __launch_bounds__(256) sim_kernel(
    const float* __restrict__ emb,
    const float* __restrict__ summary,
    const int*   __restrict__ ptr,      // int32 (JAX x64 disabled)
    const float* __restrict__ dvec,
    const float* __restrict__ scale,
    float* __restrict__ out,
    int n_rows, int n_seg)
{
    const int warp_global = (blockIdx.x * blockDim.x + threadIdx.x) >> 5;
    const int lane = threadIdx.x & 31;
    if (warp_global >= n_rows) return;

    const int row = warp_global;
    const float sc = __ldg(scale);

    // Binary search for segment. All lanes identical -> uniform loads (L1-hit).
    int lo = 0, hi = n_seg;
    while (lo < hi) {
        int mid = (lo + hi) >> 1;
        // ptr has B+1 entries; compare against ptr[mid+1]
        if (__ldg(&ptr[mid + 1]) > row) hi = mid; else lo = mid + 1;
    }
    const int seg = lo;

    // Vector loads: emb row (streaming), summary row + d (cache-resident).
    const float4 e  = reinterpret_cast<const float4*>(emb     + (size_t)row * H_DIM)[lane];
    const float4 s  = reinterpret_cast<const float4*>(summary + (size_t)seg * H_DIM)[lane];
    const float4 dd = reinterpret_cast<const float4*>(dvec)[lane];

    // Partial self-dot (for norm) and weighted dot.
    float ds = e.x * e.x;
    ds = fmaf(e.y, e.y, ds);
    ds = fmaf(e.z, e.z, ds);
    ds = fmaf(e.w, e.w, ds);

    float dw = e.x * (dd.x * s.x);
    dw = fmaf(e.y, dd.y * s.y, dw);
    dw = fmaf(e.z, dd.z * s.z, dw);
    dw = fmaf(e.w, dd.w * s.w, dw);

    // Warp tree-reduce both sums.
    #pragma unroll
    for (int off = 16; off > 0; off >>= 1) {
        ds += __shfl_xor_sync(0xFFFFFFFFu, ds, off);
        dw += __shfl_xor_sync(0xFFFFFFFFu, dw, off);
    }

    if (lane == 0) {
        float norm = fmaxf(sqrtf(ds), EPS);
        out[row] = sc * __fdividef(dw, norm);
    }
}

extern "C" void kernel_launch(void* const* d_in, const int* in_sizes, int n_in,
                              void* d_out, int out_size)
{
    const float* emb     = (const float*)d_in[0];   // [N, H]
    const float* summary = (const float*)d_in[1];   // [B, H]
    const int*   ptr     = (const int*)d_in[2];     // [B+1] int32
    const float* dvec    = (const float*)d_in[3];   // [H]
    const float* scale   = (const float*)d_in[4];   // [1]
    float*       out     = (float*)d_out;           // [N]

    const int n_rows = in_sizes[0] / H_DIM;   // N
    const int n_seg  = in_sizes[2] - 1;       // B

    // One warp per row: 256 threads = 8 rows per block.
    const int rows_per_block = 256 / 32;
    const int blocks = (n_rows + rows_per_block - 1) / rows_per_block;
    sim_kernel<<<blocks, 256>>>(emb, summary, ptr, dvec, scale, out, n_rows, n_seg);
}

// round 3
// speedup vs baseline: 1.9243x; 1.9243x over previous
#include <cuda_runtime.h>

// Problem constants (from reference): N=1048576 rows, H=128, B=1024 segments.
#define H_DIM 128
#define EPS 1e-12f

// 4 rows per warp; each 8-lane group owns one row.
// Lane g in a group holds float4 columns {g, g+8, g+16, g+24} of its row,
// so each load round is a contiguous 128B chunk per group (coalesced).
// seg(row) = first s in [0,B) with ptr[s+1] > row  (searchsorted right).
__global__ void __launch_bounds__(256) sim_kernel(
    const float* __restrict__ emb,
    const float* __restrict__ summary,
    const int*   __restrict__ ptr,      // int32 (JAX x64 disabled)
    const float* __restrict__ dvec,
    const float* __restrict__ scale,
    float* __restrict__ out,
    int n_rows, int n_seg)
{
    const int wid  = (blockIdx.x * blockDim.x + threadIdx.x) >> 5;
    const int lane = threadIdx.x & 31;
    const int g    = lane & 7;        // position within 8-lane row group
    const int rsub = lane >> 3;       // which of the warp's 4 rows

    int row = wid * 4 + rsub;
    const bool valid = row < n_rows;
    row = min(row, n_rows - 1);

    const float sc = __ldg(scale);

    // Per-lane binary search (rows within a warp differ by <=3, so paths are
    // near-uniform; ptr is L1/L2 resident). 10 iterations for B=1024.
    int lo = 0, hi = n_seg;
    while (lo < hi) {
        int mid = (lo + hi) >> 1;
        if (__ldg(&ptr[mid + 1]) > row) hi = mid; else lo = mid + 1;
    }
    const int seg = lo;

    const float4* e4 = reinterpret_cast<const float4*>(emb)     + (size_t)row * (H_DIM / 4);
    const float4* s4 = reinterpret_cast<const float4*>(summary) + (size_t)seg * (H_DIM / 4);
    const float4* d4 = reinterpret_cast<const float4*>(dvec);

    float ds = 0.0f;   // self-dot (norm)
    float dw = 0.0f;   // weighted dot
    #pragma unroll
    for (int i = 0; i < 4; i++) {
        const int c = i * 8 + g;
        const float4 e = __ldcs(&e4[c]);   // streaming: evict-first
        const float4 s = __ldg(&s4[c]);    // cache-resident
        const float4 d = __ldg(&d4[c]);    // cache-resident

        ds = fmaf(e.x, e.x, ds);
        ds = fmaf(e.y, e.y, ds);
        ds = fmaf(e.z, e.z, ds);
        ds = fmaf(e.w, e.w, ds);

        dw = fmaf(e.x, d.x * s.x, dw);
        dw = fmaf(e.y, d.y * s.y, dw);
        dw = fmaf(e.z, d.z * s.z, dw);
        dw = fmaf(e.w, d.w * s.w, dw);
    }

    // Reduce within each 8-lane group (3 butterfly steps, both sums).
    #pragma unroll
    for (int off = 4; off > 0; off >>= 1) {
        ds += __shfl_xor_sync(0xFFFFFFFFu, ds, off);
        dw += __shfl_xor_sync(0xFFFFFFFFu, dw, off);
    }

    if (g == 0 && valid) {
        out[row] = sc * __fdividef(dw, fmaxf(sqrtf(ds), EPS));
    }
}

extern "C" void kernel_launch(void* const* d_in, const int* in_sizes, int n_in,
                              void* d_out, int out_size)
{
    const float* emb     = (const float*)d_in[0];   // [N, H]
    const float* summary = (const float*)d_in[1];   // [B, H]
    const int*   ptr     = (const int*)d_in[2];     // [B+1] int32
    const float* dvec    = (const float*)d_in[3];   // [H]
    const float* scale   = (const float*)d_in[4];   // [1]
    float*       out     = (float*)d_out;           // [N]

    const int n_rows = in_sizes[0] / H_DIM;   // N
    const int n_seg  = in_sizes[2] - 1;       // B

    // 4 rows per warp, 8 warps per block -> 32 rows per block.
    const int n_warps = (n_rows + 3) / 4;
    const int blocks  = (n_warps + 7) / 8;
    sim_kernel<<<blocks, 256>>>(emb, summary, ptr, dvec, scale, out, n_rows, n_seg);
}

// round 4
// speedup vs baseline: 2.3692x; 1.2312x over previous
#include <cuda_runtime.h>

// Problem constants (from reference): N=1048576 rows, H=128, B=1024 segments.
#define H_DIM 128
#define EPS 1e-12f
#define MAX_B 4096   // scratch sized generously vs B=1024

// Precomputed w[s,h] = d[h] * summary[s,h]  (512KB for B=1024)
__device__ float g_wbuf[MAX_B * H_DIM];

__global__ void prep_kernel(const float* __restrict__ summary,
                            const float* __restrict__ dvec,
                            int total)
{
    int i = blockIdx.x * blockDim.x + threadIdx.x;
    if (i < total)
        g_wbuf[i] = summary[i] * dvec[i & (H_DIM - 1)];
}

// 4 rows per warp; each 8-lane group owns one row.
// Lane g holds float4 columns {g, g+8, g+16, g+24} of its row.
// emb loads are issued FIRST (streaming, DRAM latency), then the binary
// search's dependent L1-hit chain overlaps them, then cache-resident w loads.
__global__ void __launch_bounds__(256) sim_kernel(
    const float* __restrict__ emb,
    const int*   __restrict__ ptr,      // int32 (JAX x64 disabled)
    const float* __restrict__ scale,
    float* __restrict__ out,
    int n_rows, int n_seg)
{
    const int wid  = (blockIdx.x * blockDim.x + threadIdx.x) >> 5;
    const int lane = threadIdx.x & 31;
    const int g    = lane & 7;        // position within 8-lane row group
    const int rsub = lane >> 3;       // which of the warp's 4 rows

    int row = wid * 4 + rsub;
    const bool valid = row < n_rows;
    row = min(row, n_rows - 1);

    const float4* e4 = reinterpret_cast<const float4*>(emb) + (size_t)row * (H_DIM / 4);

    // ---- issue all streaming loads up front (MLP_p1 = 4) ----
    const float4 e0 = __ldcs(&e4[g]);
    const float4 e1 = __ldcs(&e4[8 + g]);
    const float4 e2 = __ldcs(&e4[16 + g]);
    const float4 e3 = __ldcs(&e4[24 + g]);

    // ---- segment binary search overlaps e-load latency ----
    int lo = 0, hi = n_seg;
    while (lo < hi) {
        int mid = (lo + hi) >> 1;
        if (__ldg(&ptr[mid + 1]) > row) hi = mid; else lo = mid + 1;
    }
    const float4* w4 = reinterpret_cast<const float4*>(g_wbuf) + (size_t)lo * (H_DIM / 4);

    const float4 w0 = w4[g];
    const float4 w1 = w4[8 + g];
    const float4 w2 = w4[16 + g];
    const float4 w3 = w4[24 + g];

    const float sc = __ldg(scale);

    // Self-dot (norm) and weighted dot.
    float ds = e0.x * e0.x;
    ds = fmaf(e0.y, e0.y, ds); ds = fmaf(e0.z, e0.z, ds); ds = fmaf(e0.w, e0.w, ds);
    ds = fmaf(e1.x, e1.x, ds); ds = fmaf(e1.y, e1.y, ds); ds = fmaf(e1.z, e1.z, ds); ds = fmaf(e1.w, e1.w, ds);
    ds = fmaf(e2.x, e2.x, ds); ds = fmaf(e2.y, e2.y, ds); ds = fmaf(e2.z, e2.z, ds); ds = fmaf(e2.w, e2.w, ds);
    ds = fmaf(e3.x, e3.x, ds); ds = fmaf(e3.y, e3.y, ds); ds = fmaf(e3.z, e3.z, ds); ds = fmaf(e3.w, e3.w, ds);

    float dw = e0.x * w0.x;
    dw = fmaf(e0.y, w0.y, dw); dw = fmaf(e0.z, w0.z, dw); dw = fmaf(e0.w, w0.w, dw);
    dw = fmaf(e1.x, w1.x, dw); dw = fmaf(e1.y, w1.y, dw); dw = fmaf(e1.z, w1.z, dw); dw = fmaf(e1.w, w1.w, dw);
    dw = fmaf(e2.x, w2.x, dw); dw = fmaf(e2.y, w2.y, dw); dw = fmaf(e2.z, w2.z, dw); dw = fmaf(e2.w, w2.w, dw);
    dw = fmaf(e3.x, w3.x, dw); dw = fmaf(e3.y, w3.y, dw); dw = fmaf(e3.z, w3.z, dw); dw = fmaf(e3.w, w3.w, dw);

    // Reduce within each 8-lane group (3 butterfly steps, both sums).
    #pragma unroll
    for (int off = 4; off > 0; off >>= 1) {
        ds += __shfl_xor_sync(0xFFFFFFFFu, ds, off);
        dw += __shfl_xor_sync(0xFFFFFFFFu, dw, off);
    }

    if (g == 0 && valid) {
        out[row] = sc * __fdividef(dw, fmaxf(sqrtf(ds), EPS));
    }
}

extern "C" void kernel_launch(void* const* d_in, const int* in_sizes, int n_in,
                              void* d_out, int out_size)
{
    const float* emb     = (const float*)d_in[0];   // [N, H]
    const float* summary = (const float*)d_in[1];   // [B, H]
    const int*   ptr     = (const int*)d_in[2];     // [B+1] int32
    const float* dvec    = (const float*)d_in[3];   // [H]
    const float* scale   = (const float*)d_in[4];   // [1]
    float*       out     = (float*)d_out;           // [N]

    const int n_rows = in_sizes[0] / H_DIM;   // N
    const int n_seg  = in_sizes[2] - 1;       // B
    const int w_total = in_sizes[1];          // B*H

    prep_kernel<<<(w_total + 255) / 256, 256>>>(summary, dvec, w_total);

    // 4 rows per warp, 8 warps per block -> 32 rows per block.
    const int n_warps = (n_rows + 3) / 4;
    const int blocks  = (n_warps + 7) / 8;
    sim_kernel<<<blocks, 256>>>(emb, ptr, scale, out, n_rows, n_seg);
}

// round 5
// speedup vs baseline: 2.6338x; 1.1117x over previous
#include <cuda_runtime.h>

// Problem constants (from reference): N=1048576 rows, H=128, B=1024 segments.
#define H_DIM 128
#define EPS 1e-12f
#define MAX_B 4096          // scratch sized generously vs B=1024
#define MAX_N (1 << 20)     // N = 1048576

// Precomputed w[s,h] = d[h] * summary[s,h]  (512KB for B=1024)
__device__ float g_wbuf[MAX_B * H_DIM];
// Precomputed row -> segment id (2MB for N=1M)
__device__ unsigned short g_seg[MAX_N];

__global__ void prep_w_kernel(const float* __restrict__ summary,
                              const float* __restrict__ dvec,
                              int total)
{
    int i = blockIdx.x * blockDim.x + threadIdx.x;
    if (i < total)
        g_wbuf[i] = summary[i] * dvec[i & (H_DIM - 1)];
}

// One block per segment: fill g_seg[ptr[s]..ptr[s+1]) with s.
__global__ void prep_seg_kernel(const int* __restrict__ ptr, int n_rows)
{
    const int s     = blockIdx.x;
    const int start = ptr[s];
    const int end   = min(ptr[s + 1], n_rows);
    for (int i = start + threadIdx.x; i < end; i += blockDim.x)
        g_seg[i] = (unsigned short)s;
}

// 8 rows per warp; each 4-lane group owns one row.
// Lane g in a group holds float4 columns {g, g+4, ..., g+28} of its row.
// All 8 streaming e-loads are issued up front (MLP_p1 = 8); the seg lookup
// is a single L1-hit uint16 load; w loads are L2-resident.
__global__ void __launch_bounds__(256, 4) sim_kernel(
    const float* __restrict__ emb,
    const float* __restrict__ scale,
    float* __restrict__ out,
    int n_rows)
{
    const int wid  = (blockIdx.x * blockDim.x + threadIdx.x) >> 5;
    const int lane = threadIdx.x & 31;
    const int g    = lane & 3;        // position within 4-lane row group
    const int rsub = lane >> 2;       // which of the warp's 8 rows

    int row = wid * 8 + rsub;
    const bool valid = row < n_rows;
    row = min(row, n_rows - 1);

    const float4* e4 = reinterpret_cast<const float4*>(emb) + (size_t)row * (H_DIM / 4);

    // ---- issue all streaming loads up front ----
    float4 e[8];
    #pragma unroll
    for (int i = 0; i < 8; i++)
        e[i] = __ldcs(&e4[i * 4 + g]);

    // ---- segment lookup: one cached 2B load ----
    const int seg = (int)g_seg[row];
    const float4* w4 = reinterpret_cast<const float4*>(g_wbuf) + (size_t)seg * (H_DIM / 4);

    const float sc = __ldg(scale);

    // Self-dot (norm) — depends only on e.
    float ds = 0.0f;
    #pragma unroll
    for (int i = 0; i < 8; i++) {
        ds = fmaf(e[i].x, e[i].x, ds);
        ds = fmaf(e[i].y, e[i].y, ds);
        ds = fmaf(e[i].z, e[i].z, ds);
        ds = fmaf(e[i].w, e[i].w, ds);
    }

    // Weighted dot — w loads are L1/L2 hits, consumed immediately.
    float dw = 0.0f;
    #pragma unroll
    for (int i = 0; i < 8; i++) {
        const float4 w = __ldg(&w4[i * 4 + g]);
        dw = fmaf(e[i].x, w.x, dw);
        dw = fmaf(e[i].y, w.y, dw);
        dw = fmaf(e[i].z, w.z, dw);
        dw = fmaf(e[i].w, w.w, dw);
    }

    // Reduce within each 4-lane group (2 butterfly steps, both sums).
    #pragma unroll
    for (int off = 2; off > 0; off >>= 1) {
        ds += __shfl_xor_sync(0xFFFFFFFFu, ds, off);
        dw += __shfl_xor_sync(0xFFFFFFFFu, dw, off);
    }

    if (g == 0 && valid) {
        out[row] = sc * __fdividef(dw, fmaxf(sqrtf(ds), EPS));
    }
}

extern "C" void kernel_launch(void* const* d_in, const int* in_sizes, int n_in,
                              void* d_out, int out_size)
{
    const float* emb     = (const float*)d_in[0];   // [N, H]
    const float* summary = (const float*)d_in[1];   // [B, H]
    const int*   ptr     = (const int*)d_in[2];     // [B+1] int32
    const float* dvec    = (const float*)d_in[3];   // [H]
    const float* scale   = (const float*)d_in[4];   // [1]
    float*       out     = (float*)d_out;           // [N]

    const int n_rows  = in_sizes[0] / H_DIM;   // N
    const int n_seg   = in_sizes[2] - 1;       // B
    const int w_total = in_sizes[1];           // B*H

    prep_w_kernel<<<(w_total + 255) / 256, 256>>>(summary, dvec, w_total);
    prep_seg_kernel<<<n_seg, 256>>>(ptr, n_rows);

    // 8 rows per warp, 8 warps per block -> 64 rows per block.
    const int n_warps = (n_rows + 7) / 8;
    const int blocks  = (n_warps + 7) / 8;
    sim_kernel<<<blocks, 256>>>(emb, scale, out, n_rows);
}

// round 6
// speedup vs baseline: 2.6593x; 1.0097x over previous
#include <cuda_runtime.h>

// Problem constants (from reference): N=1048576 rows, H=128, B=1024 segments.
#define H_DIM 128
#define EPS 1e-12f
#define MAX_B 4096          // scratch sized generously vs B=1024
#define MAX_N (1 << 20)     // N = 1048576

// Precomputed w[s,h] = d[h] * summary[s,h]  (512KB for B=1024)
__device__ float g_wbuf[MAX_B * H_DIM];
// Precomputed row -> segment id (2MB for N=1M)
__device__ unsigned short g_seg[MAX_N];

// Fused prep: blocks [0, n_seg) fill the seg table (one block per segment),
// blocks [n_seg, n_seg + w_blocks) compute w = d (*) summary.
__global__ void __launch_bounds__(256) prep_kernel(
    const float* __restrict__ summary,
    const float* __restrict__ dvec,
    const int*   __restrict__ ptr,
    int n_rows, int n_seg, int w_total)
{
    const int b = blockIdx.x;
    if (b < n_seg) {
        const int start = ptr[b];
        const int end   = min(ptr[b + 1], n_rows);
        for (int i = start + (int)threadIdx.x; i < end; i += 256)
            g_seg[i] = (unsigned short)b;
    } else {
        const int i = (b - n_seg) * 256 + (int)threadIdx.x;
        if (i < w_total)
            g_wbuf[i] = summary[i] * dvec[i & (H_DIM - 1)];
    }
}

// 8 rows per warp; each 4-lane group owns one row.
// Lane g in a group holds float4 columns {g, g+4, ..., g+28} of its row.
// seg lookup (L2-hit) issued first so its latency hides under the 8
// front-batched streaming e-loads (MLP_p1 = 8).
__global__ void __launch_bounds__(256, 4) sim_kernel(
    const float* __restrict__ emb,
    const float* __restrict__ scale,
    float* __restrict__ out,
    int n_rows)
{
    const int wid  = (blockIdx.x * blockDim.x + threadIdx.x) >> 5;
    const int lane = threadIdx.x & 31;
    const int g    = lane & 3;        // position within 4-lane row group
    const int rsub = lane >> 2;       // which of the warp's 8 rows

    int row = wid * 8 + rsub;
    const bool valid = row < n_rows;
    row = min(row, n_rows - 1);

    // ---- independent cached loads issued first ----
    const int   seg = (int)g_seg[row];
    const float sc  = __ldg(scale);

    const float4* e4 = reinterpret_cast<const float4*>(emb) + (size_t)row * (H_DIM / 4);

    // ---- all streaming loads front-batched ----
    float4 e[8];
    #pragma unroll
    for (int i = 0; i < 8; i++)
        e[i] = __ldcs(&e4[i * 4 + g]);

    const float4* w4 = reinterpret_cast<const float4*>(g_wbuf) + (size_t)seg * (H_DIM / 4);

    // Self-dot (norm) — depends only on e.
    float ds = 0.0f;
    #pragma unroll
    for (int i = 0; i < 8; i++) {
        ds = fmaf(e[i].x, e[i].x, ds);
        ds = fmaf(e[i].y, e[i].y, ds);
        ds = fmaf(e[i].z, e[i].z, ds);
        ds = fmaf(e[i].w, e[i].w, ds);
    }

    // Weighted dot — w loads are L1/L2 hits, consumed immediately.
    float dw = 0.0f;
    #pragma unroll
    for (int i = 0; i < 8; i++) {
        const float4 w = __ldg(&w4[i * 4 + g]);
        dw = fmaf(e[i].x, w.x, dw);
        dw = fmaf(e[i].y, w.y, dw);
        dw = fmaf(e[i].z, w.z, dw);
        dw = fmaf(e[i].w, w.w, dw);
    }

    // Reduce within each 4-lane group (2 butterfly steps, both sums).
    #pragma unroll
    for (int off = 2; off > 0; off >>= 1) {
        ds += __shfl_xor_sync(0xFFFFFFFFu, ds, off);
        dw += __shfl_xor_sync(0xFFFFFFFFu, dw, off);
    }

    if (g == 0 && valid) {
        __stcs(&out[row], sc * __fdividef(dw, fmaxf(sqrtf(ds), EPS)));
    }
}

extern "C" void kernel_launch(void* const* d_in, const int* in_sizes, int n_in,
                              void* d_out, int out_size)
{
    const float* emb     = (const float*)d_in[0];   // [N, H]
    const float* summary = (const float*)d_in[1];   // [B, H]
    const int*   ptr     = (const int*)d_in[2];     // [B+1] int32
    const float* dvec    = (const float*)d_in[3];   // [H]
    const float* scale   = (const float*)d_in[4];   // [1]
    float*       out     = (float*)d_out;           // [N]

    const int n_rows  = in_sizes[0] / H_DIM;   // N
    const int n_seg   = in_sizes[2] - 1;       // B
    const int w_total = in_sizes[1];           // B*H

    const int w_blocks = (w_total + 255) / 256;
    prep_kernel<<<n_seg + w_blocks, 256>>>(summary, dvec, ptr, n_rows, n_seg, w_total);

    // 8 rows per warp, 8 warps per block -> 64 rows per block.
    const int n_warps = (n_rows + 7) / 8;
    const int blocks  = (n_warps + 7) / 8;
    sim_kernel<<<blocks, 256>>>(emb, scale, out, n_rows);
}